// round 3
// baseline (speedup 1.0000x reference)
#include <cuda_runtime.h>

#define CB 64
#define CN 197
#define CE 768
#define CH 12
#define CHD 64
#define CT 30
#define ROWS (CB*CN)   // 12608

// Scratch (device globals: allocation-free rule)
__device__ float g_Q[ROWS*CE];
__device__ float g_K[ROWS*CE];
__device__ float g_V[ROWS*CE];
__device__ float g_O[ROWS*CE];

// ---------------------------------------------------------------------------
// SGEMM: C[M,N] = A[M,K] @ B[K,N] (+bias), row-major. 128x128 tile, BK=8,
// 256 threads, 8x8 per-thread microtile.
// ---------------------------------------------------------------------------
#define BM 128
#define BN 128
#define BKK 8

__global__ __launch_bounds__(256) void sgemm_kernel(
    const float* __restrict__ A, const float* __restrict__ Bw,
    const float* __restrict__ bias, float* __restrict__ C,
    int M, int N, int K)
{
    __shared__ float As[BKK][BM];
    __shared__ float Bs[BKK][BN];
    int tid = threadIdx.x;
    int bx = blockIdx.x, by = blockIdx.y;

    int aRow = tid >> 1;
    int aCol = (tid & 1) * 4;
    int bRow = tid >> 5;
    int bCol = (tid & 31) * 4;
    int ty = (tid >> 4) * 8;
    int tx = (tid & 15) * 8;

    int gArow = by*BM + aRow;
    bool aValid = gArow < M;
    const float* Aptr = A + (size_t)(aValid ? gArow : 0) * K + aCol;
    const float* Bptr = Bw + (size_t)bRow * N + bx*BN + bCol;

    float acc[8][8];
    #pragma unroll
    for (int i=0;i<8;i++)
        #pragma unroll
        for (int j=0;j<8;j++) acc[i][j] = 0.f;

    for (int k0 = 0; k0 < K; k0 += BKK) {
        float4 a4 = aValid ? *(const float4*)(Aptr + k0) : make_float4(0.f,0.f,0.f,0.f);
        float4 b4 = *(const float4*)(Bptr + (size_t)k0 * N);
        As[aCol+0][aRow] = a4.x;
        As[aCol+1][aRow] = a4.y;
        As[aCol+2][aRow] = a4.z;
        As[aCol+3][aRow] = a4.w;
        *(float4*)&Bs[bRow][bCol] = b4;
        __syncthreads();
        #pragma unroll
        for (int kk = 0; kk < BKK; kk++) {
            float ar[8], br[8];
            #pragma unroll
            for (int i=0;i<8;i++) ar[i] = As[kk][ty+i];
            #pragma unroll
            for (int j=0;j<8;j++) br[j] = Bs[kk][tx+j];
            #pragma unroll
            for (int i=0;i<8;i++)
                #pragma unroll
                for (int j=0;j<8;j++)
                    acc[i][j] += ar[i]*br[j];
        }
        __syncthreads();
    }

    #pragma unroll
    for (int i=0;i<8;i++) {
        int row = by*BM + ty + i;
        if (row >= M) continue;
        float* Crow = C + (size_t)row*N + bx*BN + tx;
        #pragma unroll
        for (int j=0;j<8;j+=4) {
            float4 o;
            o.x = acc[i][j+0]; o.y = acc[i][j+1]; o.z = acc[i][j+2]; o.w = acc[i][j+3];
            if (bias) {
                int col = bx*BN + tx + j;
                o.x += bias[col+0]; o.y += bias[col+1];
                o.z += bias[col+2]; o.w += bias[col+3];
            }
            *(float4*)(Crow + j) = o;
        }
    }
}

// ---------------------------------------------------------------------------
// Fused attention per (b,h): scores = (Q Kᵀ)*0.125 + (pv[iv]+ph[ih])*0.125,
// softmax (unnormalized; 1/sum folded into output), out = P·V + bins·rv.
// 8 warps, 4 query rows per warp per group.
// ---------------------------------------------------------------------------
#define PAD 68       // K rows: 17 float4 per row -> conflict-free float4 reads
#define VPAD 64      // V rows: unpadded; float2 lane-contiguous reads
#define NWARP 8
#define SMEM_ATTN_FLOATS (CN*PAD + CN*VPAD + 2*64*CT + 2*CT*64 + NWARP*4*64 + NWARP*4*200 + 4*NWARP*4*32)
#define SMEM_ATTN (SMEM_ATTN_FLOATS*4)

__global__ __launch_bounds__(256) void attn_kernel(
    const float* __restrict__ rkv, const float* __restrict__ rkh,
    const float* __restrict__ rvv, const float* __restrict__ rvh)
{
    extern __shared__ float sm[];
    float* Ks   = sm;                     // [197][68]
    float* Vs   = Ks + CN*PAD;            // [197][64]
    float* rkvT = Vs + CN*VPAD;           // [64][30] transposed
    float* rkhT = rkvT + 64*CT;
    float* rvvs = rkhT + 64*CT;           // [30][64]
    float* rvhs = rvvs + CT*64;
    float* qs   = rvhs + CT*64;           // [8][4][64]
    float* pb   = qs + NWARP*4*64;        // [8][4][200]
    float* pvb  = pb + NWARP*4*200;       // [8][4][32]
    float* phb  = pvb + NWARP*4*32;
    float* avb  = phb + NWARP*4*32;
    float* ahb  = avb + NWARP*4*32;

    int bh = blockIdx.x;
    int b = bh / CH, h = bh % CH;
    size_t base = (size_t)b*CN*CE + (size_t)h*CHD;
    int tid = threadIdx.x;

    for (int idx = tid; idx < CN*CHD; idx += 256) {
        int j = idx >> 6, d = idx & 63;
        Ks[j*PAD+d]  = g_K[base + (size_t)j*CE + d];
        Vs[j*VPAD+d] = g_V[base + (size_t)j*CE + d];
    }
    for (int idx = tid; idx < CT*CHD; idx += 256) {
        int t = idx >> 6, d = idx & 63;
        rkvT[d*CT+t] = rkv[idx];
        rkhT[d*CT+t] = rkh[idx];
        rvvs[idx] = rvv[idx];
        rvhs[idx] = rvh[idx];
    }
    __syncthreads();

    int warp = tid >> 5, lane = tid & 31;
    float* qw  = qs  + warp*4*64;
    float* pw  = pb  + warp*4*200;
    float* pvw = pvb + warp*4*32;
    float* phw = phb + warp*4*32;
    float* avw = avb + warp*4*32;
    float* ahw = ahb + warp*4*32;

    for (int g = warp; g < 50; g += NWARP) {
        int r0 = g*4;

        // ---- load q rows (zero for out-of-range rows); zero bins ----
        #pragma unroll
        for (int rr = 0; rr < 4; rr++) {
            int r = r0 + rr;
            float v0 = 0.f, v1 = 0.f;
            if (r < CN) {
                v0 = g_Q[base + (size_t)r*CE + lane];
                v1 = g_Q[base + (size_t)r*CE + lane + 32];
            }
            qw[rr*64+lane]    = v0;
            qw[rr*64+lane+32] = v1;
            avw[rr*32+lane] = 0.f;
            ahw[rr*32+lane] = 0.f;
        }
        __syncwarp();

        // ---- pv/ph: q dot rel-pos key tables (30 dots of 64) ----
        if (lane < CT) {
            float sv[4] = {0,0,0,0}, shv[4] = {0,0,0,0};
            for (int d = 0; d < CHD; d++) {
                float tv = rkvT[d*CT+lane];
                float th = rkhT[d*CT+lane];
                #pragma unroll
                for (int rr = 0; rr < 4; rr++) {
                    float qd = qw[rr*64+d];
                    sv[rr]  += qd*tv;
                    shv[rr] += qd*th;
                }
            }
            #pragma unroll
            for (int rr = 0; rr < 4; rr++) {
                pvw[rr*32+lane] = sv[rr];
                phw[rr*32+lane] = shv[rr];
            }
        }
        __syncwarp();

        int riv[4], rih[4];
        #pragma unroll
        for (int rr = 0; rr < 4; rr++) {
            int r = r0 + rr;
            int rm1 = (r >= 1) ? (r-1) : 0;
            riv[rr] = rm1 / 14;
            rih[rr] = rm1 % 14;
        }

        // ---- scores + running max ----
        float mx[4] = {-1e30f,-1e30f,-1e30f,-1e30f};
        for (int j = lane; j < CN; j += 32) {
            float s[4] = {0,0,0,0};
            const float4* K4 = (const float4*)(Ks + j*PAD);
            const float4* q4 = (const float4*)qw;
            #pragma unroll
            for (int d4 = 0; d4 < 16; d4++) {
                float4 k = K4[d4];
                #pragma unroll
                for (int rr = 0; rr < 4; rr++) {
                    float4 q = q4[rr*16+d4];
                    s[rr] += q.x*k.x + q.y*k.y + q.z*k.z + q.w*k.w;
                }
            }
            int jm1 = (j >= 1) ? (j-1) : 0;
            int jv = jm1 / 14, jh = jm1 % 14;
            #pragma unroll
            for (int rr = 0; rr < 4; rr++) {
                int r = r0 + rr;
                int iv = 0, ih = 0;
                if (r != 0 && j != 0) {
                    int dv = jv - riv[rr]; dv = max(-14, min(14, dv)); iv = dv + 15;
                    int dh = jh - rih[rr]; dh = max(-14, min(14, dh)); ih = dh + 15;
                }
                float sc = (s[rr] + pvw[rr*32+iv] + phw[rr*32+ih]) * 0.125f;
                pw[rr*200+j] = sc;
                mx[rr] = fmaxf(mx[rr], sc);
            }
        }
        #pragma unroll
        for (int rr = 0; rr < 4; rr++)
            #pragma unroll
            for (int off = 16; off > 0; off >>= 1)
                mx[rr] = fmaxf(mx[rr], __shfl_xor_sync(0xffffffffu, mx[rr], off));

        // ---- exp, bin into 30 v/h buckets, sum ----
        float sum[4] = {0,0,0,0};
        for (int j = lane; j < CN; j += 32) {
            int jm1 = (j >= 1) ? (j-1) : 0;
            int jv = jm1 / 14, jh = jm1 % 14;
            #pragma unroll
            for (int rr = 0; rr < 4; rr++) {
                float e = __expf(pw[rr*200+j] - mx[rr]);
                pw[rr*200+j] = e;
                sum[rr] += e;
                int r = r0 + rr;
                int iv = 0, ih = 0;
                if (r != 0 && j != 0) {
                    int dv = jv - riv[rr]; dv = max(-14, min(14, dv)); iv = dv + 15;
                    int dh = jh - rih[rr]; dh = max(-14, min(14, dh)); ih = dh + 15;
                }
                atomicAdd(&avw[rr*32+iv], e);
                atomicAdd(&ahw[rr*32+ih], e);
            }
        }
        #pragma unroll
        for (int rr = 0; rr < 4; rr++)
            #pragma unroll
            for (int off = 16; off > 0; off >>= 1)
                sum[rr] += __shfl_xor_sync(0xffffffffu, sum[rr], off);
        __syncwarp();

        // ---- output: P·V + bins·rv tables, normalize by 1/sum ----
        float2 o[4];
        #pragma unroll
        for (int rr = 0; rr < 4; rr++) { o[rr].x = 0.f; o[rr].y = 0.f; }
        const float2* V2 = (const float2*)Vs;   // row stride 32 float2
        for (int j = 0; j < CN; j++) {
            float2 v = V2[j*32 + lane];
            #pragma unroll
            for (int rr = 0; rr < 4; rr++) {
                float p = pw[rr*200+j];
                o[rr].x += p*v.x;
                o[rr].y += p*v.y;
            }
        }
        const float2* RV = (const float2*)rvvs; // row stride 32 float2
        const float2* RH = (const float2*)rvhs;
        for (int t = 0; t < CT; t++) {
            float2 rv = RV[t*32 + lane];
            float2 rh = RH[t*32 + lane];
            #pragma unroll
            for (int rr = 0; rr < 4; rr++) {
                float wv = avw[rr*32+t];
                float wh = ahw[rr*32+t];
                o[rr].x += wv*rv.x + wh*rh.x;
                o[rr].y += wv*rv.y + wh*rh.y;
            }
        }
        #pragma unroll
        for (int rr = 0; rr < 4; rr++) {
            int r = r0 + rr;
            if (r < CN) {
                float inv = 1.0f / sum[rr];
                float2 res; res.x = o[rr].x*inv; res.y = o[rr].y*inv;
                *(float2*)(&g_O[base + (size_t)r*CE + lane*2]) = res;
            }
        }
        __syncwarp();
    }
}

// ---------------------------------------------------------------------------
// Launch
// ---------------------------------------------------------------------------
extern "C" void kernel_launch(void* const* d_in, const int* in_sizes, int n_in,
                              void* d_out, int out_size)
{
    const float* x     = (const float*)d_in[0];
    const float* wq    = (const float*)d_in[1];
    const float* wk    = (const float*)d_in[2];
    const float* wv    = (const float*)d_in[3];
    const float* wproj = (const float*)d_in[4];
    const float* bproj = (const float*)d_in[5];
    const float* rkv   = (const float*)d_in[6];
    const float* rkh   = (const float*)d_in[7];
    const float* rvv   = (const float*)d_in[8];
    const float* rvh   = (const float*)d_in[9];
    float* out = (float*)d_out;

    float *Qp, *Kp, *Vp, *Op;
    cudaGetSymbolAddress((void**)&Qp, g_Q);
    cudaGetSymbolAddress((void**)&Kp, g_K);
    cudaGetSymbolAddress((void**)&Vp, g_V);
    cudaGetSymbolAddress((void**)&Op, g_O);

    cudaFuncSetAttribute(attn_kernel, cudaFuncAttributeMaxDynamicSharedMemorySize, SMEM_ATTN);

    dim3 blk(256);
    dim3 grid(CE/BN, (ROWS + BM - 1)/BM);
    sgemm_kernel<<<grid, blk>>>(x, wq, nullptr, Qp, ROWS, CE, CE);
    sgemm_kernel<<<grid, blk>>>(x, wk, nullptr, Kp, ROWS, CE, CE);
    sgemm_kernel<<<grid, blk>>>(x, wv, nullptr, Vp, ROWS, CE, CE);
    attn_kernel<<<CB*CH, 256, SMEM_ATTN>>>(rkv, rkh, rvv, rvh);
    sgemm_kernel<<<grid, blk>>>(Op, wproj, bproj, out, ROWS, CE, CE);
}

// round 6
// speedup vs baseline: 1.4783x; 1.4783x over previous
#include <cuda_runtime.h>
#include <cuda_bf16.h>
#include <cstdint>

#define CB 64
#define CN 197
#define CE 768
#define CH 12
#define CHD 64
#define CT 30
#define ROWS (CB*CN)   // 12608

// ---------------------------------------------------------------------------
// Device-global scratch (allocation-free rule)
// ---------------------------------------------------------------------------
__device__ float g_Q[ROWS*CE];
__device__ float g_K[ROWS*CE];
__device__ float g_V[ROWS*CE];
__device__ float g_O[ROWS*CE];
__device__ __nv_bfloat16 g_Ah[ROWS*CE];
__device__ __nv_bfloat16 g_Al[ROWS*CE];
__device__ __nv_bfloat16 g_Wth[4*CE*CE];   // q,k,v,proj transposed hi
__device__ __nv_bfloat16 g_Wtl[4*CE*CE];   // lo

// ---------------------------------------------------------------------------
// Warp-MMA helpers (base ISA: sm_80+; compiles for sm_100 target)
// ---------------------------------------------------------------------------
__device__ __forceinline__ uint32_t smem_to_u32(const void* p) {
    uint32_t a;
    asm("{ .reg .u64 t; cvta.to.shared.u64 t, %1; cvt.u32.u64 %0, t; }" : "=r"(a) : "l"(p));
    return a;
}
__device__ __forceinline__ void ldsm_x4(uint32_t* r, uint32_t addr) {
    asm volatile("ldmatrix.sync.aligned.m8n8.x4.shared.b16 {%0,%1,%2,%3}, [%4];"
                 : "=r"(r[0]), "=r"(r[1]), "=r"(r[2]), "=r"(r[3]) : "r"(addr));
}
__device__ __forceinline__ void ldsm_x2(uint32_t* r, uint32_t addr) {
    asm volatile("ldmatrix.sync.aligned.m8n8.x2.shared.b16 {%0,%1}, [%2];"
                 : "=r"(r[0]), "=r"(r[1]) : "r"(addr));
}
__device__ __forceinline__ void mma_bf16(float* c, const uint32_t* a, const uint32_t* b) {
    asm volatile(
        "mma.sync.aligned.m16n8k16.row.col.f32.bf16.bf16.f32 "
        "{%0,%1,%2,%3}, {%4,%5,%6,%7}, {%8,%9}, {%0,%1,%2,%3};"
        : "+f"(c[0]), "+f"(c[1]), "+f"(c[2]), "+f"(c[3])
        : "r"(a[0]), "r"(a[1]), "r"(a[2]), "r"(a[3]), "r"(b[0]), "r"(b[1]));
}
__device__ __forceinline__ void cp_async16(uint32_t smem_addr, const void* gptr) {
    asm volatile("cp.async.cg.shared.global [%0], [%1], 16;" :: "r"(smem_addr), "l"(gptr));
}
#define CP_COMMIT()  asm volatile("cp.async.commit_group;")
#define CP_WAIT(N)   asm volatile("cp.async.wait_group %0;" :: "n"(N))

// ---------------------------------------------------------------------------
// Preprocessing kernels
// ---------------------------------------------------------------------------
__global__ void split_x_kernel(const float* __restrict__ X,
                               __nv_bfloat16* __restrict__ H, __nv_bfloat16* __restrict__ L, int n)
{
    int i = blockIdx.x*blockDim.x + threadIdx.x;
    if (i < n) {
        float v = X[i];
        __nv_bfloat16 h = __float2bfloat16(v);
        __nv_bfloat16 l = __float2bfloat16(v - __bfloat162float(h));
        H[i] = h; L[i] = l;
    }
}

// W[K][N] (row-major) -> Wt[N][K] split into hi/lo
__global__ void transpose_split_w(const float* __restrict__ W,
                                  __nv_bfloat16* __restrict__ Th, __nv_bfloat16* __restrict__ Tl)
{
    __shared__ float t[32][33];
    int n0 = blockIdx.x*32, k0 = blockIdx.y*32;
    int tx = threadIdx.x, ty = threadIdx.y;   // (32,8)
    for (int i = ty; i < 32; i += 8)
        t[i][tx] = W[(size_t)(k0+i)*CE + n0+tx];
    __syncthreads();
    for (int i = ty; i < 32; i += 8) {
        float v = t[tx][i];   // W[k0+tx][n0+i]
        __nv_bfloat16 h = __float2bfloat16(v);
        __nv_bfloat16 l = __float2bfloat16(v - __bfloat162float(h));
        Th[(size_t)(n0+i)*CE + k0+tx] = h;
        Tl[(size_t)(n0+i)*CE + k0+tx] = l;
    }
}

// ---------------------------------------------------------------------------
// Split-bf16 GEMM via mma.sync: C[M,768] = A[M,768] @ W[768,768] (+bias)
// A as hi/lo bf16 [M][768]; W transposed hi/lo bf16 [768][768] ([n][k]).
// 128x128 CTA tile, 8 warps (2x4), 64x32 warp tile, K chunk 64,
// cp.async double buffering.
// ---------------------------------------------------------------------------
#define GKC 64
#define NCHUNK (CE/GKC)         // 12
#define APAD 72                  // bf16 per smem row (64 + 8 pad)
#define TILE_E (128*APAD)        // 9216 bf16 elems per tile
#define BUF_E (4*TILE_E)         // Ah,Al,Bh,Bl
#define GEMM_SMEM (2*BUF_E*2)    // bytes = 147456

__global__ __launch_bounds__(256) void gemm_mma(
    const __nv_bfloat16* __restrict__ Ah, const __nv_bfloat16* __restrict__ Al,
    const __nv_bfloat16* __restrict__ Bh, const __nv_bfloat16* __restrict__ Bl,
    const float* __restrict__ bias, float* __restrict__ C, int M)
{
    extern __shared__ __nv_bfloat16 smb[];
    uint32_t smem_base = smem_to_u32(smb);
    int tid = threadIdx.x;
    int wid = tid >> 5, lane = tid & 31;
    int m0 = blockIdx.y * 128;
    int n0 = blockIdx.x * 128;
    int mBase = (wid >> 2) * 64;
    int nBase = (wid & 3) * 32;

    float acc[4][4][4];
    #pragma unroll
    for (int mi=0;mi<4;mi++)
        #pragma unroll
        for (int ni=0;ni<4;ni++)
            #pragma unroll
            for (int q=0;q<4;q++) acc[mi][ni][q] = 0.f;

    // per-thread load coords (4 uint4 rows-of-8 per tile)
    int lrow[4], lc8[4];
    #pragma unroll
    for (int t=0;t<4;t++) { int e = tid + t*256; lrow[t] = e>>3; lc8[t] = e&7; }

    // issue chunk loads into buffer buf
    auto issue_chunk = [&](int chunk, int buf) {
        int k0 = chunk * GKC;
        uint32_t sb = smem_base + (uint32_t)buf * BUF_E * 2;
        #pragma unroll
        for (int t=0;t<4;t++) {
            int row = lrow[t], c8 = lc8[t];
            uint32_t so = (uint32_t)(row*APAD + c8*8)*2;
            int gm = m0 + row; if (gm >= M) gm = M-1;
            size_t aoff = (size_t)gm*CE + k0 + c8*8;
            cp_async16(sb + 0*TILE_E*2 + so, Ah + aoff);
            cp_async16(sb + 1*TILE_E*2 + so, Al + aoff);
            int gn = n0 + row;
            size_t boff = (size_t)gn*CE + k0 + c8*8;
            cp_async16(sb + 2*TILE_E*2 + so, Bh + boff);
            cp_async16(sb + 3*TILE_E*2 + so, Bl + boff);
        }
        CP_COMMIT();
    };

    issue_chunk(0, 0);

    int buf = 0;
    for (int chunk = 0; chunk < NCHUNK; chunk++) {
        if (chunk + 1 < NCHUNK) {
            issue_chunk(chunk + 1, buf ^ 1);
            CP_WAIT(1);
        } else {
            CP_WAIT(0);
        }
        __syncthreads();

        uint32_t sb = smem_base + (uint32_t)buf * BUF_E * 2;
        uint32_t aHb = sb + 0*TILE_E*2;
        uint32_t aLb = sb + 1*TILE_E*2;
        uint32_t bHb = sb + 2*TILE_E*2;
        uint32_t bLb = sb + 3*TILE_E*2;

        int arow = mBase + (lane & 15);
        int acolsel = ((lane >> 4) & 1) << 3;
        int brow = nBase + (lane & 7);
        int bcolsel = ((lane >> 3) & 1) << 3;

        #pragma unroll
        for (int kk = 0; kk < 4; kk++) {
            int kc = kk * 16;
            uint32_t ah[4][4], al[4][4], bh[4][2], bl[4][2];
            #pragma unroll
            for (int mi = 0; mi < 4; mi++) {
                uint32_t off = (uint32_t)((arow + mi*16)*APAD + kc + acolsel)*2;
                ldsm_x4(ah[mi], aHb + off);
                ldsm_x4(al[mi], aLb + off);
            }
            #pragma unroll
            for (int ni = 0; ni < 4; ni++) {
                uint32_t off = (uint32_t)((brow + ni*8)*APAD + kc + bcolsel)*2;
                ldsm_x2(bh[ni], bHb + off);
                ldsm_x2(bl[ni], bLb + off);
            }
            #pragma unroll
            for (int mi = 0; mi < 4; mi++)
                #pragma unroll
                for (int ni = 0; ni < 4; ni++) {
                    mma_bf16(acc[mi][ni], ah[mi], bh[ni]);
                    mma_bf16(acc[mi][ni], ah[mi], bl[ni]);
                    mma_bf16(acc[mi][ni], al[mi], bh[ni]);
                }
        }
        __syncthreads();
        buf ^= 1;
    }

    // epilogue: c0=(m,n) c1=(m,n+1) c2=(m+8,n) c3=(m+8,n+1)
    int tg = lane >> 2, tn = (lane & 3) * 2;
    #pragma unroll
    for (int mi = 0; mi < 4; mi++) {
        int m = m0 + mBase + mi*16 + tg;
        #pragma unroll
        for (int ni = 0; ni < 4; ni++) {
            int n = n0 + nBase + ni*8 + tn;
            float b0 = bias ? bias[n]   : 0.f;
            float b1 = bias ? bias[n+1] : 0.f;
            if (m < M) {
                float2 o; o.x = acc[mi][ni][0] + b0; o.y = acc[mi][ni][1] + b1;
                *(float2*)(C + (size_t)m*CE + n) = o;
            }
            if (m + 8 < M) {
                float2 o; o.x = acc[mi][ni][2] + b0; o.y = acc[mi][ni][3] + b1;
                *(float2*)(C + (size_t)(m+8)*CE + n) = o;
            }
        }
    }
}

// ---------------------------------------------------------------------------
// Fused attention per (b,h) — unchanged (verified in round 3)
// ---------------------------------------------------------------------------
#define PAD 68
#define VPAD 64
#define NWARP 8
#define SMEM_ATTN_FLOATS (CN*PAD + CN*VPAD + 2*64*CT + 2*CT*64 + NWARP*4*64 + NWARP*4*200 + 4*NWARP*4*32)
#define SMEM_ATTN (SMEM_ATTN_FLOATS*4)

__global__ __launch_bounds__(256) void attn_kernel(
    const float* __restrict__ rkv, const float* __restrict__ rkh,
    const float* __restrict__ rvv, const float* __restrict__ rvh)
{
    extern __shared__ float sm[];
    float* Ks   = sm;
    float* Vs   = Ks + CN*PAD;
    float* rkvT = Vs + CN*VPAD;
    float* rkhT = rkvT + 64*CT;
    float* rvvs = rkhT + 64*CT;
    float* rvhs = rvvs + CT*64;
    float* qs   = rvhs + CT*64;
    float* pb   = qs + NWARP*4*64;
    float* pvb  = pb + NWARP*4*200;
    float* phb  = pvb + NWARP*4*32;
    float* avb  = phb + NWARP*4*32;
    float* ahb  = avb + NWARP*4*32;

    int bh = blockIdx.x;
    int b = bh / CH, h = bh % CH;
    size_t base = (size_t)b*CN*CE + (size_t)h*CHD;
    int tid = threadIdx.x;

    for (int idx = tid; idx < CN*CHD; idx += 256) {
        int j = idx >> 6, d = idx & 63;
        Ks[j*PAD+d]  = g_K[base + (size_t)j*CE + d];
        Vs[j*VPAD+d] = g_V[base + (size_t)j*CE + d];
    }
    for (int idx = tid; idx < CT*CHD; idx += 256) {
        int t = idx >> 6, d = idx & 63;
        rkvT[d*CT+t] = rkv[idx];
        rkhT[d*CT+t] = rkh[idx];
        rvvs[idx] = rvv[idx];
        rvhs[idx] = rvh[idx];
    }
    __syncthreads();

    int warp = tid >> 5, lane = tid & 31;
    float* qw  = qs  + warp*4*64;
    float* pw  = pb  + warp*4*200;
    float* pvw = pvb + warp*4*32;
    float* phw = phb + warp*4*32;
    float* avw = avb + warp*4*32;
    float* ahw = ahb + warp*4*32;

    for (int g = warp; g < 50; g += NWARP) {
        int r0 = g*4;

        #pragma unroll
        for (int rr = 0; rr < 4; rr++) {
            int r = r0 + rr;
            float v0 = 0.f, v1 = 0.f;
            if (r < CN) {
                v0 = g_Q[base + (size_t)r*CE + lane];
                v1 = g_Q[base + (size_t)r*CE + lane + 32];
            }
            qw[rr*64+lane]    = v0;
            qw[rr*64+lane+32] = v1;
            avw[rr*32+lane] = 0.f;
            ahw[rr*32+lane] = 0.f;
        }
        __syncwarp();

        if (lane < CT) {
            float sv[4] = {0,0,0,0}, shv[4] = {0,0,0,0};
            for (int d = 0; d < CHD; d++) {
                float tv = rkvT[d*CT+lane];
                float th = rkhT[d*CT+lane];
                #pragma unroll
                for (int rr = 0; rr < 4; rr++) {
                    float qd = qw[rr*64+d];
                    sv[rr]  += qd*tv;
                    shv[rr] += qd*th;
                }
            }
            #pragma unroll
            for (int rr = 0; rr < 4; rr++) {
                pvw[rr*32+lane] = sv[rr];
                phw[rr*32+lane] = shv[rr];
            }
        }
        __syncwarp();

        int riv[4], rih[4];
        #pragma unroll
        for (int rr = 0; rr < 4; rr++) {
            int r = r0 + rr;
            int rm1 = (r >= 1) ? (r-1) : 0;
            riv[rr] = rm1 / 14;
            rih[rr] = rm1 % 14;
        }

        float mx[4] = {-1e30f,-1e30f,-1e30f,-1e30f};
        for (int j = lane; j < CN; j += 32) {
            float s[4] = {0,0,0,0};
            const float4* K4 = (const float4*)(Ks + j*PAD);
            const float4* q4 = (const float4*)qw;
            #pragma unroll
            for (int d4 = 0; d4 < 16; d4++) {
                float4 k = K4[d4];
                #pragma unroll
                for (int rr = 0; rr < 4; rr++) {
                    float4 q = q4[rr*16+d4];
                    s[rr] += q.x*k.x + q.y*k.y + q.z*k.z + q.w*k.w;
                }
            }
            int jm1 = (j >= 1) ? (j-1) : 0;
            int jv = jm1 / 14, jh = jm1 % 14;
            #pragma unroll
            for (int rr = 0; rr < 4; rr++) {
                int r = r0 + rr;
                int iv = 0, ih = 0;
                if (r != 0 && j != 0) {
                    int dv = jv - riv[rr]; dv = max(-14, min(14, dv)); iv = dv + 15;
                    int dh = jh - rih[rr]; dh = max(-14, min(14, dh)); ih = dh + 15;
                }
                float sc = (s[rr] + pvw[rr*32+iv] + phw[rr*32+ih]) * 0.125f;
                pw[rr*200+j] = sc;
                mx[rr] = fmaxf(mx[rr], sc);
            }
        }
        #pragma unroll
        for (int rr = 0; rr < 4; rr++)
            #pragma unroll
            for (int off = 16; off > 0; off >>= 1)
                mx[rr] = fmaxf(mx[rr], __shfl_xor_sync(0xffffffffu, mx[rr], off));

        float sum[4] = {0,0,0,0};
        for (int j = lane; j < CN; j += 32) {
            int jm1 = (j >= 1) ? (j-1) : 0;
            int jv = jm1 / 14, jh = jm1 % 14;
            #pragma unroll
            for (int rr = 0; rr < 4; rr++) {
                float e = __expf(pw[rr*200+j] - mx[rr]);
                pw[rr*200+j] = e;
                sum[rr] += e;
                int r = r0 + rr;
                int iv = 0, ih = 0;
                if (r != 0 && j != 0) {
                    int dv = jv - riv[rr]; dv = max(-14, min(14, dv)); iv = dv + 15;
                    int dh = jh - rih[rr]; dh = max(-14, min(14, dh)); ih = dh + 15;
                }
                atomicAdd(&avw[rr*32+iv], e);
                atomicAdd(&ahw[rr*32+ih], e);
            }
        }
        #pragma unroll
        for (int rr = 0; rr < 4; rr++)
            #pragma unroll
            for (int off = 16; off > 0; off >>= 1)
                sum[rr] += __shfl_xor_sync(0xffffffffu, sum[rr], off);
        __syncwarp();

        float2 o[4];
        #pragma unroll
        for (int rr = 0; rr < 4; rr++) { o[rr].x = 0.f; o[rr].y = 0.f; }
        const float2* V2 = (const float2*)Vs;
        for (int j = 0; j < CN; j++) {
            float2 v = V2[j*32 + lane];
            #pragma unroll
            for (int rr = 0; rr < 4; rr++) {
                float p = pw[rr*200+j];
                o[rr].x += p*v.x;
                o[rr].y += p*v.y;
            }
        }
        const float2* RV = (const float2*)rvvs;
        const float2* RH = (const float2*)rvhs;
        for (int t = 0; t < CT; t++) {
            float2 rv = RV[t*32 + lane];
            float2 rh = RH[t*32 + lane];
            #pragma unroll
            for (int rr = 0; rr < 4; rr++) {
                float wv = avw[rr*32+t];
                float wh = ahw[rr*32+t];
                o[rr].x += wv*rv.x + wh*rh.x;
                o[rr].y += wv*rv.y + wh*rh.y;
            }
        }
        #pragma unroll
        for (int rr = 0; rr < 4; rr++) {
            int r = r0 + rr;
            if (r < CN) {
                float inv = 1.0f / sum[rr];
                float2 res; res.x = o[rr].x*inv; res.y = o[rr].y*inv;
                *(float2*)(&g_O[base + (size_t)r*CE + lane*2]) = res;
            }
        }
        __syncwarp();
    }
}

// ---------------------------------------------------------------------------
// Launch
// ---------------------------------------------------------------------------
extern "C" void kernel_launch(void* const* d_in, const int* in_sizes, int n_in,
                              void* d_out, int out_size)
{
    const float* x     = (const float*)d_in[0];
    const float* wq    = (const float*)d_in[1];
    const float* wk    = (const float*)d_in[2];
    const float* wv    = (const float*)d_in[3];
    const float* wproj = (const float*)d_in[4];
    const float* bproj = (const float*)d_in[5];
    const float* rkv   = (const float*)d_in[6];
    const float* rkh   = (const float*)d_in[7];
    const float* rvv   = (const float*)d_in[8];
    const float* rvh   = (const float*)d_in[9];
    float* out = (float*)d_out;

    float *Qp, *Kp, *Vp, *Op;
    __nv_bfloat16 *Ahp, *Alp, *Wthp, *Wtlp;
    cudaGetSymbolAddress((void**)&Qp, g_Q);
    cudaGetSymbolAddress((void**)&Kp, g_K);
    cudaGetSymbolAddress((void**)&Vp, g_V);
    cudaGetSymbolAddress((void**)&Op, g_O);
    cudaGetSymbolAddress((void**)&Ahp, g_Ah);
    cudaGetSymbolAddress((void**)&Alp, g_Al);
    cudaGetSymbolAddress((void**)&Wthp, g_Wth);
    cudaGetSymbolAddress((void**)&Wtlp, g_Wtl);

    cudaFuncSetAttribute(attn_kernel, cudaFuncAttributeMaxDynamicSharedMemorySize, SMEM_ATTN);
    cudaFuncSetAttribute(gemm_mma, cudaFuncAttributeMaxDynamicSharedMemorySize, GEMM_SMEM);

    // 1. transpose+split the 4 weights
    {
        dim3 tb(32, 8), tg(CE/32, CE/32);
        transpose_split_w<<<tg, tb>>>(wq,    Wthp + 0ull*CE*CE, Wtlp + 0ull*CE*CE);
        transpose_split_w<<<tg, tb>>>(wk,    Wthp + 1ull*CE*CE, Wtlp + 1ull*CE*CE);
        transpose_split_w<<<tg, tb>>>(wv,    Wthp + 2ull*CE*CE, Wtlp + 2ull*CE*CE);
        transpose_split_w<<<tg, tb>>>(wproj, Wthp + 3ull*CE*CE, Wtlp + 3ull*CE*CE);
    }
    // 2. split x
    int nel = ROWS*CE;
    split_x_kernel<<<(nel+255)/256, 256>>>(x, Ahp, Alp, nel);

    // 3. Q/K/V projections on tensor cores (mma.sync)
    dim3 gg(CE/128, (ROWS + 127)/128);   // (6, 99)
    gemm_mma<<<gg, 256, GEMM_SMEM>>>(Ahp, Alp, Wthp + 0ull*CE*CE, Wtlp + 0ull*CE*CE, nullptr, Qp, ROWS);
    gemm_mma<<<gg, 256, GEMM_SMEM>>>(Ahp, Alp, Wthp + 1ull*CE*CE, Wtlp + 1ull*CE*CE, nullptr, Kp, ROWS);
    gemm_mma<<<gg, 256, GEMM_SMEM>>>(Ahp, Alp, Wthp + 2ull*CE*CE, Wtlp + 2ull*CE*CE, nullptr, Vp, ROWS);

    // 4. attention
    attn_kernel<<<CB*CH, 256, SMEM_ATTN>>>(rkv, rkh, rvv, rvh);

    // 5. split O, 6. output projection (+bias)
    split_x_kernel<<<(nel+255)/256, 256>>>(Op, Ahp, Alp, nel);
    gemm_mma<<<gg, 256, GEMM_SMEM>>>(Ahp, Alp, Wthp + 3ull*CE*CE, Wtlp + 3ull*CE*CE, bproj, out, ROWS);
}

// round 7
// speedup vs baseline: 2.5968x; 1.7566x over previous
#include <cuda_runtime.h>
#include <cuda_bf16.h>
#include <cstdint>

#define CB 64
#define CN 197
#define CE 768
#define CH 12
#define CHD 64
#define CT 30
#define ROWS (CB*CN)   // 12608

// ---------------------------------------------------------------------------
// Device-global scratch (allocation-free rule)
// ---------------------------------------------------------------------------
__device__ float g_Q[ROWS*CE];
__device__ float g_K[ROWS*CE];
__device__ float g_V[ROWS*CE];
__device__ float g_O[ROWS*CE];
__device__ __nv_bfloat16 g_Ah[ROWS*CE];
__device__ __nv_bfloat16 g_Al[ROWS*CE];
__device__ __nv_bfloat16 g_Wth[4*CE*CE];   // q,k,v,proj transposed hi
__device__ __nv_bfloat16 g_Wtl[4*CE*CE];   // lo

// ---------------------------------------------------------------------------
// Warp-MMA helpers (base ISA: sm_80+)
// ---------------------------------------------------------------------------
__device__ __forceinline__ uint32_t smem_to_u32(const void* p) {
    uint32_t a;
    asm("{ .reg .u64 t; cvta.to.shared.u64 t, %1; cvt.u32.u64 %0, t; }" : "=r"(a) : "l"(p));
    return a;
}
__device__ __forceinline__ void ldsm_x4(uint32_t* r, uint32_t addr) {
    asm volatile("ldmatrix.sync.aligned.m8n8.x4.shared.b16 {%0,%1,%2,%3}, [%4];"
                 : "=r"(r[0]), "=r"(r[1]), "=r"(r[2]), "=r"(r[3]) : "r"(addr));
}
__device__ __forceinline__ void ldsm_x2(uint32_t* r, uint32_t addr) {
    asm volatile("ldmatrix.sync.aligned.m8n8.x2.shared.b16 {%0,%1}, [%2];"
                 : "=r"(r[0]), "=r"(r[1]) : "r"(addr));
}
__device__ __forceinline__ void mma_bf16(float* c, const uint32_t* a, const uint32_t* b) {
    asm volatile(
        "mma.sync.aligned.m16n8k16.row.col.f32.bf16.bf16.f32 "
        "{%0,%1,%2,%3}, {%4,%5,%6,%7}, {%8,%9}, {%0,%1,%2,%3};"
        : "+f"(c[0]), "+f"(c[1]), "+f"(c[2]), "+f"(c[3])
        : "r"(a[0]), "r"(a[1]), "r"(a[2]), "r"(a[3]), "r"(b[0]), "r"(b[1]));
}
__device__ __forceinline__ void cp_async16(uint32_t smem_addr, const void* gptr) {
    asm volatile("cp.async.cg.shared.global [%0], [%1], 16;" :: "r"(smem_addr), "l"(gptr));
}
#define CP_COMMIT()  asm volatile("cp.async.commit_group;")
#define CP_WAIT(N)   asm volatile("cp.async.wait_group %0;" :: "n"(N))

// ---------------------------------------------------------------------------
// Preprocessing kernels
// ---------------------------------------------------------------------------
__global__ void split_x_kernel(const float* __restrict__ X,
                               __nv_bfloat16* __restrict__ H, __nv_bfloat16* __restrict__ L, int n)
{
    int i = blockIdx.x*blockDim.x + threadIdx.x;
    if (i < n) {
        float v = X[i];
        __nv_bfloat16 h = __float2bfloat16(v);
        __nv_bfloat16 l = __float2bfloat16(v - __bfloat162float(h));
        H[i] = h; L[i] = l;
    }
}

__global__ void transpose_split_w(const float* __restrict__ W,
                                  __nv_bfloat16* __restrict__ Th, __nv_bfloat16* __restrict__ Tl)
{
    __shared__ float t[32][33];
    int n0 = blockIdx.x*32, k0 = blockIdx.y*32;
    int tx = threadIdx.x, ty = threadIdx.y;   // (32,8)
    for (int i = ty; i < 32; i += 8)
        t[i][tx] = W[(size_t)(k0+i)*CE + n0+tx];
    __syncthreads();
    for (int i = ty; i < 32; i += 8) {
        float v = t[tx][i];
        __nv_bfloat16 h = __float2bfloat16(v);
        __nv_bfloat16 l = __float2bfloat16(v - __bfloat162float(h));
        Th[(size_t)(n0+i)*CE + k0+tx] = h;
        Tl[(size_t)(n0+i)*CE + k0+tx] = l;
    }
}

// ---------------------------------------------------------------------------
// Split-bf16 GEMM via mma.sync. 128x128 CTA tile, 8 warps, K chunk 32,
// cp.async double buffering, 2 CTAs/SM.
// ---------------------------------------------------------------------------
#define GKC 32
#define NCHUNK (CE/GKC)          // 24
#define APAD 40                  // bf16 per smem row (32 + 8 pad) -> 80B rows
#define TILE_E (128*APAD)        // 5120 bf16 per tile
#define BUF_E (4*TILE_E)         // Ah,Al,Bh,Bl
#define GEMM_SMEM (2*BUF_E*2)    // 81920 bytes

__global__ __launch_bounds__(256, 2) void gemm_mma(
    const __nv_bfloat16* __restrict__ Ah, const __nv_bfloat16* __restrict__ Al,
    const __nv_bfloat16* __restrict__ Bh, const __nv_bfloat16* __restrict__ Bl,
    const float* __restrict__ bias, float* __restrict__ C, int M)
{
    extern __shared__ __nv_bfloat16 smb[];
    uint32_t smem_base = smem_to_u32(smb);
    int tid = threadIdx.x;
    int wid = tid >> 5, lane = tid & 31;
    int m0 = blockIdx.y * 128;
    int n0 = blockIdx.x * 128;
    int mBase = (wid >> 2) * 64;
    int nBase = (wid & 3) * 32;

    float acc[4][4][4];
    #pragma unroll
    for (int mi=0;mi<4;mi++)
        #pragma unroll
        for (int ni=0;ni<4;ni++)
            #pragma unroll
            for (int q=0;q<4;q++) acc[mi][ni][q] = 0.f;

    // per-thread load coords: tile = 128 rows x 4 uint4; 2 per thread
    int lrow[2], lc4[2];
    #pragma unroll
    for (int t=0;t<2;t++) { int e = tid + t*256; lrow[t] = e>>2; lc4[t] = e&3; }

    auto issue_chunk = [&](int chunk, int buf) {
        int k0 = chunk * GKC;
        uint32_t sb = smem_base + (uint32_t)buf * BUF_E * 2;
        #pragma unroll
        for (int t=0;t<2;t++) {
            int row = lrow[t], c4 = lc4[t];
            uint32_t so = (uint32_t)(row*APAD + c4*8)*2;
            int gm = m0 + row; if (gm >= M) gm = M-1;
            size_t aoff = (size_t)gm*CE + k0 + c4*8;
            cp_async16(sb + 0*TILE_E*2 + so, Ah + aoff);
            cp_async16(sb + 1*TILE_E*2 + so, Al + aoff);
            int gn = n0 + row;
            size_t boff = (size_t)gn*CE + k0 + c4*8;
            cp_async16(sb + 2*TILE_E*2 + so, Bh + boff);
            cp_async16(sb + 3*TILE_E*2 + so, Bl + boff);
        }
        CP_COMMIT();
    };

    issue_chunk(0, 0);

    int buf = 0;
    for (int chunk = 0; chunk < NCHUNK; chunk++) {
        if (chunk + 1 < NCHUNK) {
            issue_chunk(chunk + 1, buf ^ 1);
            CP_WAIT(1);
        } else {
            CP_WAIT(0);
        }
        __syncthreads();

        uint32_t sb = smem_base + (uint32_t)buf * BUF_E * 2;
        uint32_t aHb = sb + 0*TILE_E*2;
        uint32_t aLb = sb + 1*TILE_E*2;
        uint32_t bHb = sb + 2*TILE_E*2;
        uint32_t bLb = sb + 3*TILE_E*2;

        int arow = mBase + (lane & 15);
        int acolsel = ((lane >> 4) & 1) << 3;
        int brow = nBase + (lane & 7);
        int bcolsel = ((lane >> 3) & 1) << 3;

        #pragma unroll
        for (int kk = 0; kk < 2; kk++) {
            int kc = kk * 16;
            uint32_t af[4][4], bf[4][2];
            // --- term 1: Ah * Bh ---
            #pragma unroll
            for (int mi = 0; mi < 4; mi++)
                ldsm_x4(af[mi], aHb + (uint32_t)((arow + mi*16)*APAD + kc + acolsel)*2);
            #pragma unroll
            for (int ni = 0; ni < 4; ni++)
                ldsm_x2(bf[ni], bHb + (uint32_t)((brow + ni*8)*APAD + kc + bcolsel)*2);
            #pragma unroll
            for (int mi = 0; mi < 4; mi++)
                #pragma unroll
                for (int ni = 0; ni < 4; ni++)
                    mma_bf16(acc[mi][ni], af[mi], bf[ni]);
            // --- term 2: Ah * Bl (reuse af) ---
            #pragma unroll
            for (int ni = 0; ni < 4; ni++)
                ldsm_x2(bf[ni], bLb + (uint32_t)((brow + ni*8)*APAD + kc + bcolsel)*2);
            #pragma unroll
            for (int mi = 0; mi < 4; mi++)
                #pragma unroll
                for (int ni = 0; ni < 4; ni++)
                    mma_bf16(acc[mi][ni], af[mi], bf[ni]);
            // --- term 3: Al * Bh (reload both) ---
            #pragma unroll
            for (int mi = 0; mi < 4; mi++)
                ldsm_x4(af[mi], aLb + (uint32_t)((arow + mi*16)*APAD + kc + acolsel)*2);
            #pragma unroll
            for (int ni = 0; ni < 4; ni++)
                ldsm_x2(bf[ni], bHb + (uint32_t)((brow + ni*8)*APAD + kc + bcolsel)*2);
            #pragma unroll
            for (int mi = 0; mi < 4; mi++)
                #pragma unroll
                for (int ni = 0; ni < 4; ni++)
                    mma_bf16(acc[mi][ni], af[mi], bf[ni]);
        }
        __syncthreads();
        buf ^= 1;
    }

    int tg = lane >> 2, tn = (lane & 3) * 2;
    #pragma unroll
    for (int mi = 0; mi < 4; mi++) {
        int m = m0 + mBase + mi*16 + tg;
        #pragma unroll
        for (int ni = 0; ni < 4; ni++) {
            int n = n0 + nBase + ni*8 + tn;
            float b0 = bias ? bias[n]   : 0.f;
            float b1 = bias ? bias[n+1] : 0.f;
            if (m < M) {
                float2 o; o.x = acc[mi][ni][0] + b0; o.y = acc[mi][ni][1] + b1;
                *(float2*)(C + (size_t)m*CE + n) = o;
            }
            if (m + 8 < M) {
                float2 o; o.x = acc[mi][ni][2] + b0; o.y = acc[mi][ni][3] + b1;
                *(float2*)(C + (size_t)(m+8)*CE + n) = o;
            }
        }
    }
}

// ---------------------------------------------------------------------------
// Fused attention per (b,h) — v2: 16 warps, 2 rows/warp, no atomics,
// registers kept low (scores s[7][2] only).
// ---------------------------------------------------------------------------
#define KPAD 68
#define ANW 16
#define ATHREADS 512
// floats: Ks + Vs + 4 tables + qs + pw + pv + ph + gs + cs
#define ASMEM_FLOATS (CN*KPAD + CN*64 + 4*CT*64 + ANW*2*64 + ANW*2*200 + 2*ANW*2*32 + 2*ANW*2*16)
#define ASMEM (ASMEM_FLOATS*4)

__global__ __launch_bounds__(ATHREADS, 1) void attn_kernel(
    const float* __restrict__ rkv, const float* __restrict__ rkh,
    const float* __restrict__ rvv, const float* __restrict__ rvh)
{
    extern __shared__ float sm[];
    float* Ks   = sm;                      // [197][68]
    float* Vs   = Ks + CN*KPAD;            // [197][64]
    float* rkvT = Vs + CN*64;              // [64][30]
    float* rkhT = rkvT + 64*CT;
    float* rvvs = rkhT + 64*CT;            // [30][64]
    float* rvhs = rvvs + CT*64;
    float* qs   = rvhs + CT*64;            // [16][2][64]
    float* pb   = qs + ANW*2*64;           // [16][2][200]
    float* pvb  = pb + ANW*2*200;          // [16][2][32]
    float* phb  = pvb + ANW*2*32;
    float* gsb  = phb + ANW*2*32;          // [16][2][16]
    float* csb  = gsb + ANW*2*16;

    int bh = blockIdx.x;
    int b = bh / CH, h = bh % CH;
    size_t base = (size_t)b*CN*CE + (size_t)h*CHD;
    int tid = threadIdx.x;

    for (int idx = tid; idx < CN*CHD; idx += ATHREADS) {
        int j = idx >> 6, d = idx & 63;
        Ks[j*KPAD+d] = g_K[base + (size_t)j*CE + d];
        Vs[j*64+d]   = g_V[base + (size_t)j*CE + d];
    }
    for (int idx = tid; idx < CT*CHD; idx += ATHREADS) {
        int t = idx >> 6, d = idx & 63;
        rkvT[d*CT+t] = rkv[idx];
        rkhT[d*CT+t] = rkh[idx];
        rvvs[idx] = rvv[idx];
        rvhs[idx] = rvh[idx];
    }
    __syncthreads();

    int warp = tid >> 5, lane = tid & 31;
    float* qw  = qs  + warp*2*64;
    float* pw  = pb  + warp*2*200;
    float* pvw = pvb + warp*2*32;
    float* phw = phb + warp*2*32;
    float* gsw = gsb + warp*2*16;
    float* csw = csb + warp*2*16;

    // per-lane j coordinates (j = lane + 32*jj), fixed across groups
    int jvv[7], jhh[7];
    #pragma unroll
    for (int jj = 0; jj < 7; jj++) {
        int j = lane + jj*32;
        int jm1 = (j >= 1) ? (j-1) : 0;
        jvv[jj] = jm1 / 14;
        jhh[jj] = jm1 % 14;
    }

    const float2* V2  = (const float2*)Vs;
    const float2* RV2 = (const float2*)rvvs;
    const float2* RH2 = (const float2*)rvhs;

    for (int g = warp; g < 99; g += ANW) {
        int r0 = g*2;
        bool val0 = (r0 < CN), val1 = (r0+1 < CN);

        // ---- q rows to smem ----
        {
            float a0=0.f,a1=0.f,b0=0.f,b1=0.f;
            if (val0) { a0 = g_Q[base + (size_t)r0*CE + lane]; a1 = g_Q[base + (size_t)r0*CE + lane + 32]; }
            if (val1) { b0 = g_Q[base + (size_t)(r0+1)*CE + lane]; b1 = g_Q[base + (size_t)(r0+1)*CE + lane + 32]; }
            qw[lane] = a0; qw[lane+32] = a1;
            qw[64+lane] = b0; qw[64+lane+32] = b1;
        }
        __syncwarp();

        // ---- pv/ph tables: 30 dots of 64, per row ----
        if (lane < CT) {
            float sv0=0.f, sh0=0.f, sv1=0.f, sh1=0.f;
            #pragma unroll 4
            for (int d = 0; d < CHD; d++) {
                float tv = rkvT[d*CT+lane];
                float th = rkhT[d*CT+lane];
                float q0 = qw[d], q1 = qw[64+d];
                sv0 += q0*tv; sh0 += q0*th;
                sv1 += q1*tv; sh1 += q1*th;
            }
            pvw[lane] = sv0; phw[lane] = sh0;
            pvw[32+lane] = sv1; phw[32+lane] = sh1;
        }
        __syncwarp();

        int riv0, rih0, riv1, rih1;
        { int rm1 = (r0 >= 1) ? (r0-1) : 0; riv0 = rm1/14; rih0 = rm1%14; }
        { int rm1 = r0; riv1 = rm1/14; rih1 = rm1%14; }   // row r0+1 >= 1 always

        // ---- scores: d4-outer, j-inner; only s[7][2] live ----
        float s[7][2];
        #pragma unroll
        for (int jj=0;jj<7;jj++){ s[jj][0]=0.f; s[jj][1]=0.f; }
        const float4* q40 = (const float4*)qw;
        const float4* q41 = (const float4*)(qw+64);
        #pragma unroll
        for (int d4 = 0; d4 < 16; d4++) {
            float4 q0 = q40[d4];
            float4 q1 = q41[d4];
            #pragma unroll
            for (int jj = 0; jj < 7; jj++) {
                int j = lane + jj*32;
                int jc = (j < CN) ? j : (CN-1);
                float4 k = ((const float4*)(Ks + jc*KPAD))[d4];
                s[jj][0] += q0.x*k.x + q0.y*k.y + q0.z*k.z + q0.w*k.w;
                s[jj][1] += q1.x*k.x + q1.y*k.y + q1.z*k.z + q1.w*k.w;
            }
        }

        // ---- bias + scale + mask; running max ----
        float mx0 = -1e30f, mx1 = -1e30f;
        #pragma unroll
        for (int jj = 0; jj < 7; jj++) {
            int j = lane + jj*32;
            if (j < CN) {
                int iv0 = (r0 != 0 && j != 0) ? (jvv[jj] - riv0 + 15) : 0;
                int ih0 = (r0 != 0 && j != 0) ? (jhh[jj] - rih0 + 15) : 0;
                int iv1 = (j != 0) ? (jvv[jj] - riv1 + 15) : 0;
                int ih1 = (j != 0) ? (jhh[jj] - rih1 + 15) : 0;
                s[jj][0] = (s[jj][0] + pvw[iv0] + phw[ih0]) * 0.125f;
                s[jj][1] = (s[jj][1] + pvw[32+iv1] + phw[32+ih1]) * 0.125f;
                mx0 = fmaxf(mx0, s[jj][0]);
                mx1 = fmaxf(mx1, s[jj][1]);
            } else {
                s[jj][0] = -1e30f; s[jj][1] = -1e30f;
            }
        }
        #pragma unroll
        for (int off = 16; off > 0; off >>= 1) {
            mx0 = fmaxf(mx0, __shfl_xor_sync(0xffffffffu, mx0, off));
            mx1 = fmaxf(mx1, __shfl_xor_sync(0xffffffffu, mx1, off));
        }

        // ---- exp; store to pw; sum ----
        float sum0 = 0.f, sum1 = 0.f;
        #pragma unroll
        for (int jj = 0; jj < 7; jj++) {
            int j = lane + jj*32;
            if (j < CN) {
                float e0 = __expf(s[jj][0] - mx0);
                float e1 = __expf(s[jj][1] - mx1);
                pw[j] = e0; pw[200+j] = e1;
                sum0 += e0; sum1 += e1;
            }
        }
        #pragma unroll
        for (int off = 16; off > 0; off >>= 1) {
            sum0 += __shfl_xor_sync(0xffffffffu, sum0, off);
            sum1 += __shfl_xor_sync(0xffffffffu, sum1, off);
        }
        __syncwarp();

        // ---- grid-row / grid-col partial sums (replaces atomics) ----
        #pragma unroll
        for (int rr = 0; rr < 2; rr++) {
            const float* pr = pw + rr*200;
            if (lane < 14) {
                float sgs = 0.f;
                #pragma unroll 7
                for (int c = 0; c < 14; c++) sgs += pr[1 + lane*14 + c];
                gsw[rr*16+lane] = sgs;
            } else if (lane >= 16 && lane < 30) {
                int c = lane - 16;
                float scs = 0.f;
                #pragma unroll 7
                for (int gg = 0; gg < 14; gg++) scs += pr[1 + gg*14 + c];
                csw[rr*16+c] = scs;
            }
        }
        __syncwarp();

        // ---- output: P·V + rel-pos value terms, folded normalize ----
        float2 o0 = make_float2(0.f,0.f), o1 = make_float2(0.f,0.f);
        #pragma unroll 4
        for (int j = 0; j < CN; j++) {
            float2 v = V2[j*32 + lane];
            float p0 = pw[j], p1 = pw[200+j];
            o0.x += p0*v.x; o0.y += p0*v.y;
            o1.x += p1*v.x; o1.y += p1*v.y;
        }
        // row 0 special: every j maps to bin 0 for both tables
        if (r0 == 0) {
            float2 rv = RV2[lane];
            float2 rh = RH2[lane];
            o0.x += sum0*(rv.x + rh.x);
            o0.y += sum0*(rv.y + rh.y);
        } else {
            float e0 = pw[0];
            float2 rv = RV2[lane];
            float2 rh = RH2[lane];
            o0.x += e0*(rv.x + rh.x);
            o0.y += e0*(rv.y + rh.y);
            #pragma unroll 7
            for (int gg = 0; gg < 14; gg++) {
                float wv = gsw[gg];
                float wh = csw[gg];
                float2 rv2 = RV2[(gg - riv0 + 15)*32 + lane];
                float2 rh2 = RH2[(gg - rih0 + 15)*32 + lane];
                o0.x += wv*rv2.x + wh*rh2.x;
                o0.y += wv*rv2.y + wh*rh2.y;
            }
        }
        {   // row r0+1 (always != 0 when valid)
            float e0 = pw[200];
            float2 rv = RV2[lane];
            float2 rh = RH2[lane];
            o1.x += e0*(rv.x + rh.x);
            o1.y += e0*(rv.y + rh.y);
            #pragma unroll 7
            for (int gg = 0; gg < 14; gg++) {
                float wv = gsw[16+gg];
                float wh = csw[16+gg];
                float2 rv2 = RV2[(gg - riv1 + 15)*32 + lane];
                float2 rh2 = RH2[(gg - rih1 + 15)*32 + lane];
                o1.x += wv*rv2.x + wh*rh2.x;
                o1.y += wv*rv2.y + wh*rh2.y;
            }
        }
        if (val0) {
            float inv = 1.0f / sum0;
            float2 res; res.x = o0.x*inv; res.y = o0.y*inv;
            *(float2*)(&g_O[base + (size_t)r0*CE + lane*2]) = res;
        }
        if (val1) {
            float inv = 1.0f / sum1;
            float2 res; res.x = o1.x*inv; res.y = o1.y*inv;
            *(float2*)(&g_O[base + (size_t)(r0+1)*CE + lane*2]) = res;
        }
        __syncwarp();
    }
}

// ---------------------------------------------------------------------------
// Launch
// ---------------------------------------------------------------------------
extern "C" void kernel_launch(void* const* d_in, const int* in_sizes, int n_in,
                              void* d_out, int out_size)
{
    const float* x     = (const float*)d_in[0];
    const float* wq    = (const float*)d_in[1];
    const float* wk    = (const float*)d_in[2];
    const float* wv    = (const float*)d_in[3];
    const float* wproj = (const float*)d_in[4];
    const float* bproj = (const float*)d_in[5];
    const float* rkv   = (const float*)d_in[6];
    const float* rkh   = (const float*)d_in[7];
    const float* rvv   = (const float*)d_in[8];
    const float* rvh   = (const float*)d_in[9];
    float* out = (float*)d_out;

    float *Qp, *Kp, *Vp, *Op;
    __nv_bfloat16 *Ahp, *Alp, *Wthp, *Wtlp;
    cudaGetSymbolAddress((void**)&Qp, g_Q);
    cudaGetSymbolAddress((void**)&Kp, g_K);
    cudaGetSymbolAddress((void**)&Vp, g_V);
    cudaGetSymbolAddress((void**)&Op, g_O);
    cudaGetSymbolAddress((void**)&Ahp, g_Ah);
    cudaGetSymbolAddress((void**)&Alp, g_Al);
    cudaGetSymbolAddress((void**)&Wthp, g_Wth);
    cudaGetSymbolAddress((void**)&Wtlp, g_Wtl);

    cudaFuncSetAttribute(attn_kernel, cudaFuncAttributeMaxDynamicSharedMemorySize, ASMEM);
    cudaFuncSetAttribute(gemm_mma, cudaFuncAttributeMaxDynamicSharedMemorySize, GEMM_SMEM);

    {
        dim3 tb(32, 8), tg(CE/32, CE/32);
        transpose_split_w<<<tg, tb>>>(wq,    Wthp + 0ull*CE*CE, Wtlp + 0ull*CE*CE);
        transpose_split_w<<<tg, tb>>>(wk,    Wthp + 1ull*CE*CE, Wtlp + 1ull*CE*CE);
        transpose_split_w<<<tg, tb>>>(wv,    Wthp + 2ull*CE*CE, Wtlp + 2ull*CE*CE);
        transpose_split_w<<<tg, tb>>>(wproj, Wthp + 3ull*CE*CE, Wtlp + 3ull*CE*CE);
    }
    int nel = ROWS*CE;
    split_x_kernel<<<(nel+255)/256, 256>>>(x, Ahp, Alp, nel);

    dim3 gg(CE/128, (ROWS + 127)/128);   // (6, 99)
    gemm_mma<<<gg, 256, GEMM_SMEM>>>(Ahp, Alp, Wthp + 0ull*CE*CE, Wtlp + 0ull*CE*CE, nullptr, Qp, ROWS);
    gemm_mma<<<gg, 256, GEMM_SMEM>>>(Ahp, Alp, Wthp + 1ull*CE*CE, Wtlp + 1ull*CE*CE, nullptr, Kp, ROWS);
    gemm_mma<<<gg, 256, GEMM_SMEM>>>(Ahp, Alp, Wthp + 2ull*CE*CE, Wtlp + 2ull*CE*CE, nullptr, Vp, ROWS);

    attn_kernel<<<CB*CH, ATHREADS, ASMEM>>>(rkv, rkh, rvv, rvh);

    split_x_kernel<<<(nel+255)/256, 256>>>(Op, Ahp, Alp, nel);
    gemm_mma<<<gg, 256, GEMM_SMEM>>>(Ahp, Alp, Wthp + 3ull*CE*CE, Wtlp + 3ull*CE*CE, bproj, out, ROWS);
}

// round 8
// speedup vs baseline: 2.8925x; 1.1139x over previous
#include <cuda_runtime.h>
#include <cuda_bf16.h>
#include <cstdint>

#define CB 64
#define CN 197
#define CE 768
#define CH 12
#define CHD 64
#define CT 30
#define ROWS (CB*CN)   // 12608

// ---------------------------------------------------------------------------
// Device-global scratch (allocation-free rule)
// ---------------------------------------------------------------------------
__device__ float g_Q[ROWS*CE];
__device__ float g_K[ROWS*CE];
__device__ float g_V[ROWS*CE];
__device__ __nv_bfloat16 g_Ah[ROWS*CE];
__device__ __nv_bfloat16 g_Al[ROWS*CE];
__device__ __nv_bfloat16 g_Wth[4*CE*CE];   // [q|k|v|proj] transposed hi: rows 0..3071
__device__ __nv_bfloat16 g_Wtl[4*CE*CE];   // lo

// ---------------------------------------------------------------------------
// Warp-MMA helpers (base ISA: sm_80+)
// ---------------------------------------------------------------------------
__device__ __forceinline__ uint32_t smem_to_u32(const void* p) {
    uint32_t a;
    asm("{ .reg .u64 t; cvta.to.shared.u64 t, %1; cvt.u32.u64 %0, t; }" : "=r"(a) : "l"(p));
    return a;
}
__device__ __forceinline__ void ldsm_x4(uint32_t* r, uint32_t addr) {
    asm volatile("ldmatrix.sync.aligned.m8n8.x4.shared.b16 {%0,%1,%2,%3}, [%4];"
                 : "=r"(r[0]), "=r"(r[1]), "=r"(r[2]), "=r"(r[3]) : "r"(addr));
}
__device__ __forceinline__ void ldsm_x2(uint32_t* r, uint32_t addr) {
    asm volatile("ldmatrix.sync.aligned.m8n8.x2.shared.b16 {%0,%1}, [%2];"
                 : "=r"(r[0]), "=r"(r[1]) : "r"(addr));
}
__device__ __forceinline__ void mma_bf16(float* c, const uint32_t* a, const uint32_t* b) {
    asm volatile(
        "mma.sync.aligned.m16n8k16.row.col.f32.bf16.bf16.f32 "
        "{%0,%1,%2,%3}, {%4,%5,%6,%7}, {%8,%9}, {%0,%1,%2,%3};"
        : "+f"(c[0]), "+f"(c[1]), "+f"(c[2]), "+f"(c[3])
        : "r"(a[0]), "r"(a[1]), "r"(a[2]), "r"(a[3]), "r"(b[0]), "r"(b[1]));
}
__device__ __forceinline__ void cp_async16(uint32_t smem_addr, const void* gptr) {
    asm volatile("cp.async.cg.shared.global [%0], [%1], 16;" :: "r"(smem_addr), "l"(gptr));
}
#define CP_COMMIT()  asm volatile("cp.async.commit_group;")
#define CP_WAIT(N)   asm volatile("cp.async.wait_group %0;" :: "n"(N))

// ---------------------------------------------------------------------------
// Preprocessing kernels
// ---------------------------------------------------------------------------
__global__ void split_x_kernel(const float* __restrict__ X,
                               __nv_bfloat16* __restrict__ H, __nv_bfloat16* __restrict__ L, int n)
{
    int i = blockIdx.x*blockDim.x + threadIdx.x;
    if (i < n) {
        float v = X[i];
        __nv_bfloat16 h = __float2bfloat16(v);
        __nv_bfloat16 l = __float2bfloat16(v - __bfloat162float(h));
        H[i] = h; L[i] = l;
    }
}

// all 4 weights transposed+split in one launch (blockIdx.z selects weight)
__global__ void transpose_split_w4(const float* __restrict__ w0, const float* __restrict__ w1,
                                   const float* __restrict__ w2, const float* __restrict__ w3,
                                   __nv_bfloat16* __restrict__ Th, __nv_bfloat16* __restrict__ Tl)
{
    __shared__ float t[32][33];
    int z = blockIdx.z;
    const float* W = (z==0) ? w0 : (z==1) ? w1 : (z==2) ? w2 : w3;
    __nv_bfloat16* Tho = Th + (size_t)z*CE*CE;
    __nv_bfloat16* Tlo = Tl + (size_t)z*CE*CE;
    int n0 = blockIdx.x*32, k0 = blockIdx.y*32;
    int tx = threadIdx.x, ty = threadIdx.y;   // (32,8)
    for (int i = ty; i < 32; i += 8)
        t[i][tx] = W[(size_t)(k0+i)*CE + n0+tx];
    __syncthreads();
    for (int i = ty; i < 32; i += 8) {
        float v = t[tx][i];
        __nv_bfloat16 h = __float2bfloat16(v);
        __nv_bfloat16 l = __float2bfloat16(v - __bfloat162float(h));
        Tho[(size_t)(n0+i)*CE + k0+tx] = h;
        Tlo[(size_t)(n0+i)*CE + k0+tx] = l;
    }
}

// ---------------------------------------------------------------------------
// Split-bf16 GEMM via mma.sync. 128x128 CTA tile, 8 warps, K chunk 32,
// cp.async double buffering, 2 CTAs/SM. Epilogue routes output by
// blockIdx.x/6 into C0/C1/C2 (fused QKV); proj uses grid.x=6 -> C0 only.
// ---------------------------------------------------------------------------
#define GKC 32
#define NCHUNK (CE/GKC)          // 24
#define APAD 40                  // bf16 per smem row (32 + 8 pad)
#define TILE_E (128*APAD)        // 5120 bf16 per tile
#define BUF_E (4*TILE_E)
#define GEMM_SMEM (2*BUF_E*2)    // 81920 bytes

__global__ __launch_bounds__(256, 2) void gemm_mma(
    const __nv_bfloat16* __restrict__ Ah, const __nv_bfloat16* __restrict__ Al,
    const __nv_bfloat16* __restrict__ Bh, const __nv_bfloat16* __restrict__ Bl,
    const float* __restrict__ bias,
    float* __restrict__ C0, float* __restrict__ C1, float* __restrict__ C2, int M)
{
    extern __shared__ __nv_bfloat16 smb[];
    uint32_t smem_base = smem_to_u32(smb);
    int tid = threadIdx.x;
    int wid = tid >> 5, lane = tid & 31;
    int m0 = blockIdx.y * 128;
    int n0 = blockIdx.x * 128;          // row into B (0..2303 for fused)
    int mBase = (wid >> 2) * 64;
    int nBase = (wid & 3) * 32;

    float acc[4][4][4];
    #pragma unroll
    for (int mi=0;mi<4;mi++)
        #pragma unroll
        for (int ni=0;ni<4;ni++)
            #pragma unroll
            for (int q=0;q<4;q++) acc[mi][ni][q] = 0.f;

    int lrow[2], lc4[2];
    #pragma unroll
    for (int t=0;t<2;t++) { int e = tid + t*256; lrow[t] = e>>2; lc4[t] = e&3; }

    auto issue_chunk = [&](int chunk, int buf) {
        int k0 = chunk * GKC;
        uint32_t sb = smem_base + (uint32_t)buf * BUF_E * 2;
        #pragma unroll
        for (int t=0;t<2;t++) {
            int row = lrow[t], c4 = lc4[t];
            uint32_t so = (uint32_t)(row*APAD + c4*8)*2;
            int gm = m0 + row; if (gm >= M) gm = M-1;
            size_t aoff = (size_t)gm*CE + k0 + c4*8;
            cp_async16(sb + 0*TILE_E*2 + so, Ah + aoff);
            cp_async16(sb + 1*TILE_E*2 + so, Al + aoff);
            int gn = n0 + row;
            size_t boff = (size_t)gn*CE + k0 + c4*8;
            cp_async16(sb + 2*TILE_E*2 + so, Bh + boff);
            cp_async16(sb + 3*TILE_E*2 + so, Bl + boff);
        }
        CP_COMMIT();
    };

    issue_chunk(0, 0);

    int buf = 0;
    for (int chunk = 0; chunk < NCHUNK; chunk++) {
        if (chunk + 1 < NCHUNK) {
            issue_chunk(chunk + 1, buf ^ 1);
            CP_WAIT(1);
        } else {
            CP_WAIT(0);
        }
        __syncthreads();

        uint32_t sb = smem_base + (uint32_t)buf * BUF_E * 2;
        uint32_t aHb = sb + 0*TILE_E*2;
        uint32_t aLb = sb + 1*TILE_E*2;
        uint32_t bHb = sb + 2*TILE_E*2;
        uint32_t bLb = sb + 3*TILE_E*2;

        int arow = mBase + (lane & 15);
        int acolsel = ((lane >> 4) & 1) << 3;
        int brow = nBase + (lane & 7);
        int bcolsel = ((lane >> 3) & 1) << 3;

        #pragma unroll
        for (int kk = 0; kk < 2; kk++) {
            int kc = kk * 16;
            uint32_t af[4][4], bf[4][2];
            // term 1: Ah * Bh
            #pragma unroll
            for (int mi = 0; mi < 4; mi++)
                ldsm_x4(af[mi], aHb + (uint32_t)((arow + mi*16)*APAD + kc + acolsel)*2);
            #pragma unroll
            for (int ni = 0; ni < 4; ni++)
                ldsm_x2(bf[ni], bHb + (uint32_t)((brow + ni*8)*APAD + kc + bcolsel)*2);
            #pragma unroll
            for (int mi = 0; mi < 4; mi++)
                #pragma unroll
                for (int ni = 0; ni < 4; ni++)
                    mma_bf16(acc[mi][ni], af[mi], bf[ni]);
            // term 2: Ah * Bl (reuse af)
            #pragma unroll
            for (int ni = 0; ni < 4; ni++)
                ldsm_x2(bf[ni], bLb + (uint32_t)((brow + ni*8)*APAD + kc + bcolsel)*2);
            #pragma unroll
            for (int mi = 0; mi < 4; mi++)
                #pragma unroll
                for (int ni = 0; ni < 4; ni++)
                    mma_bf16(acc[mi][ni], af[mi], bf[ni]);
            // term 3: Al * Bh
            #pragma unroll
            for (int mi = 0; mi < 4; mi++)
                ldsm_x4(af[mi], aLb + (uint32_t)((arow + mi*16)*APAD + kc + acolsel)*2);
            #pragma unroll
            for (int ni = 0; ni < 4; ni++)
                ldsm_x2(bf[ni], bHb + (uint32_t)((brow + ni*8)*APAD + kc + bcolsel)*2);
            #pragma unroll
            for (int mi = 0; mi < 4; mi++)
                #pragma unroll
                for (int ni = 0; ni < 4; ni++)
                    mma_bf16(acc[mi][ni], af[mi], bf[ni]);
        }
        __syncthreads();
        buf ^= 1;
    }

    // epilogue: select target panel (fused QKV: bx/6 -> Q,K,V)
    int sel = blockIdx.x / 6;
    float* Cc = (sel == 0) ? C0 : (sel == 1) ? C1 : C2;
    int ncol0 = n0 - sel*768;
    int tg = lane >> 2, tn = (lane & 3) * 2;
    #pragma unroll
    for (int mi = 0; mi < 4; mi++) {
        int m = m0 + mBase + mi*16 + tg;
        #pragma unroll
        for (int ni = 0; ni < 4; ni++) {
            int n = ncol0 + nBase + ni*8 + tn;
            float b0 = bias ? bias[n]   : 0.f;
            float b1 = bias ? bias[n+1] : 0.f;
            if (m < M) {
                float2 o; o.x = acc[mi][ni][0] + b0; o.y = acc[mi][ni][1] + b1;
                *(float2*)(Cc + (size_t)m*CE + n) = o;
            }
            if (m + 8 < M) {
                float2 o; o.x = acc[mi][ni][2] + b0; o.y = acc[mi][ni][3] + b1;
                *(float2*)(Cc + (size_t)(m+8)*CE + n) = o;
            }
        }
    }
}

// ---------------------------------------------------------------------------
// Fused attention per (b,h) — v3: rotate-swizzled K smem (conflict-free
// LDS.128), hoisted row indexing, writes output directly as bf16 hi/lo.
// ---------------------------------------------------------------------------
#define ANW 16
#define ATHREADS 512
// floats: Ks[197*64] + Vs[197*64] + 4 tables + qs + pw + pv + ph + gs + cs
#define ASMEM_FLOATS (CN*64 + CN*64 + 4*CT*64 + ANW*2*64 + ANW*2*200 + 2*ANW*2*32 + 2*ANW*2*16)
#define ASMEM (ASMEM_FLOATS*4)

__global__ __launch_bounds__(ATHREADS, 1) void attn_kernel(
    const float* __restrict__ rkv, const float* __restrict__ rkh,
    const float* __restrict__ rvv, const float* __restrict__ rvh)
{
    extern __shared__ float sm[];
    float* Ks   = sm;                      // [197][64] rotate-swizzled
    float* Vs   = Ks + CN*64;              // [197][64]
    float* rkvT = Vs + CN*64;              // [64][30]
    float* rkhT = rkvT + 64*CT;
    float* rvvs = rkhT + 64*CT;            // [30][64]
    float* rvhs = rvvs + CT*64;
    float* qs   = rvhs + CT*64;            // [16][2][64]
    float* pb   = qs + ANW*2*64;           // [16][2][200]
    float* pvb  = pb + ANW*2*200;          // [16][2][32]
    float* phb  = pvb + ANW*2*32;
    float* gsb  = phb + ANW*2*32;          // [16][2][16]
    float* csb  = gsb + ANW*2*16;

    int bh = blockIdx.x;
    int b = bh / CH, h = bh % CH;
    size_t base = (size_t)b*CN*CE + (size_t)h*CHD;
    int tid = threadIdx.x;

    for (int idx = tid; idx < CN*CHD; idx += ATHREADS) {
        int j = idx >> 6, d = idx & 63;
        int d4 = d >> 2;
        Ks[j*64 + (((d4 + j) & 15) << 2) + (d & 3)] = g_K[base + (size_t)j*CE + d];
        Vs[j*64 + d] = g_V[base + (size_t)j*CE + d];
    }
    for (int idx = tid; idx < CT*CHD; idx += ATHREADS) {
        int t = idx >> 6, d = idx & 63;
        rkvT[d*CT+t] = rkv[idx];
        rkhT[d*CT+t] = rkh[idx];
        rvvs[idx] = rvv[idx];
        rvhs[idx] = rvh[idx];
    }
    __syncthreads();

    int warp = tid >> 5, lane = tid & 31;
    float* qw  = qs  + warp*2*64;
    float* pw  = pb  + warp*2*200;
    float* pvw = pvb + warp*2*32;
    float* phw = phb + warp*2*32;
    float* gsw = gsb + warp*2*16;
    float* csw = csb + warp*2*16;

    // kernel-invariant per-lane j geometry
    int jvv[7], jhh[7], kboff[7], krot[7];
    #pragma unroll
    for (int jj = 0; jj < 7; jj++) {
        int j = lane + jj*32;
        int jm1 = (j >= 1) ? (j-1) : 0;
        jvv[jj] = jm1 / 14;
        jhh[jj] = jm1 % 14;
        int jc = (j < CN) ? j : (CN-1);
        kboff[jj] = jc*64;
        krot[jj]  = jc & 15;
    }

    const float2* V2  = (const float2*)Vs;
    const float2* RV2 = (const float2*)rvvs;
    const float2* RH2 = (const float2*)rvhs;

    for (int g = warp; g < 99; g += ANW) {
        int r0 = g*2;
        bool val0 = (r0 < CN), val1 = (r0+1 < CN);

        // ---- q rows to smem ----
        {
            float a0=0.f,a1=0.f,b0=0.f,b1=0.f;
            if (val0) { a0 = g_Q[base + (size_t)r0*CE + lane]; a1 = g_Q[base + (size_t)r0*CE + lane + 32]; }
            if (val1) { b0 = g_Q[base + (size_t)(r0+1)*CE + lane]; b1 = g_Q[base + (size_t)(r0+1)*CE + lane + 32]; }
            qw[lane] = a0; qw[lane+32] = a1;
            qw[64+lane] = b0; qw[64+lane+32] = b1;
        }
        __syncwarp();

        // ---- pv/ph: 30 dots of 64 per row ----
        if (lane < CT) {
            float sv0=0.f, sh0=0.f, sv1=0.f, sh1=0.f;
            #pragma unroll 4
            for (int d = 0; d < CHD; d++) {
                float tv = rkvT[d*CT+lane];
                float th = rkhT[d*CT+lane];
                float q0 = qw[d], q1 = qw[64+d];
                sv0 += q0*tv; sh0 += q0*th;
                sv1 += q1*tv; sh1 += q1*th;
            }
            pvw[lane] = sv0; phw[lane] = sh0;
            pvw[32+lane] = sv1; phw[32+lane] = sh1;
        }
        __syncwarp();

        int riv0, rih0, riv1, rih1;
        { int rm1 = (r0 >= 1) ? (r0-1) : 0; riv0 = rm1/14; rih0 = rm1%14; }
        { int rm1 = r0; riv1 = rm1/14; rih1 = rm1%14; }

        // ---- scores (swizzled, conflict-free LDS.128) ----
        float s[7][2];
        #pragma unroll
        for (int jj=0;jj<7;jj++){ s[jj][0]=0.f; s[jj][1]=0.f; }
        const float4* q40 = (const float4*)qw;
        const float4* q41 = (const float4*)(qw+64);
        #pragma unroll
        for (int d4 = 0; d4 < 16; d4++) {
            float4 q0 = q40[d4];
            float4 q1 = q41[d4];
            #pragma unroll
            for (int jj = 0; jj < 7; jj++) {
                float4 k = *(const float4*)(Ks + kboff[jj] + (((d4 + krot[jj]) & 15) << 2));
                s[jj][0] += q0.x*k.x + q0.y*k.y + q0.z*k.z + q0.w*k.w;
                s[jj][1] += q1.x*k.x + q1.y*k.y + q1.z*k.z + q1.w*k.w;
            }
        }

        // ---- bias + scale + mask; max ----
        float mx0 = -1e30f, mx1 = -1e30f;
        #pragma unroll
        for (int jj = 0; jj < 7; jj++) {
            int j = lane + jj*32;
            if (j < CN) {
                int iv0 = (r0 != 0 && j != 0) ? (jvv[jj] - riv0 + 15) : 0;
                int ih0 = (r0 != 0 && j != 0) ? (jhh[jj] - rih0 + 15) : 0;
                int iv1 = (j != 0) ? (jvv[jj] - riv1 + 15) : 0;
                int ih1 = (j != 0) ? (jhh[jj] - rih1 + 15) : 0;
                s[jj][0] = (s[jj][0] + pvw[iv0] + phw[ih0]) * 0.125f;
                s[jj][1] = (s[jj][1] + pvw[32+iv1] + phw[32+ih1]) * 0.125f;
                mx0 = fmaxf(mx0, s[jj][0]);
                mx1 = fmaxf(mx1, s[jj][1]);
            } else {
                s[jj][0] = -1e30f; s[jj][1] = -1e30f;
            }
        }
        #pragma unroll
        for (int off = 16; off > 0; off >>= 1) {
            mx0 = fmaxf(mx0, __shfl_xor_sync(0xffffffffu, mx0, off));
            mx1 = fmaxf(mx1, __shfl_xor_sync(0xffffffffu, mx1, off));
        }

        // ---- exp; pw; sum ----
        float sum0 = 0.f, sum1 = 0.f;
        #pragma unroll
        for (int jj = 0; jj < 7; jj++) {
            int j = lane + jj*32;
            if (j < CN) {
                float e0 = __expf(s[jj][0] - mx0);
                float e1 = __expf(s[jj][1] - mx1);
                pw[j] = e0; pw[200+j] = e1;
                sum0 += e0; sum1 += e1;
            }
        }
        #pragma unroll
        for (int off = 16; off > 0; off >>= 1) {
            sum0 += __shfl_xor_sync(0xffffffffu, sum0, off);
            sum1 += __shfl_xor_sync(0xffffffffu, sum1, off);
        }
        __syncwarp();

        // ---- grid-row/col partial sums ----
        #pragma unroll
        for (int rr = 0; rr < 2; rr++) {
            const float* pr = pw + rr*200;
            if (lane < 14) {
                float sgs = 0.f;
                #pragma unroll 7
                for (int c = 0; c < 14; c++) sgs += pr[1 + lane*14 + c];
                gsw[rr*16+lane] = sgs;
            } else if (lane >= 16 && lane < 30) {
                int c = lane - 16;
                float scs = 0.f;
                #pragma unroll 7
                for (int gg = 0; gg < 14; gg++) scs += pr[1 + gg*14 + c];
                csw[rr*16+c] = scs;
            }
        }
        __syncwarp();

        // ---- output: P·V + rel-pos value terms ----
        float2 o0 = make_float2(0.f,0.f), o1 = make_float2(0.f,0.f);
        #pragma unroll 4
        for (int j = 0; j < CN; j++) {
            float2 v = V2[j*32 + lane];
            float p0 = pw[j], p1 = pw[200+j];
            o0.x += p0*v.x; o0.y += p0*v.y;
            o1.x += p1*v.x; o1.y += p1*v.y;
        }
        if (r0 == 0) {
            float2 rv = RV2[lane];
            float2 rh = RH2[lane];
            o0.x += sum0*(rv.x + rh.x);
            o0.y += sum0*(rv.y + rh.y);
        } else {
            float e0 = pw[0];
            float2 rv = RV2[lane];
            float2 rh = RH2[lane];
            o0.x += e0*(rv.x + rh.x);
            o0.y += e0*(rv.y + rh.y);
            #pragma unroll 7
            for (int gg = 0; gg < 14; gg++) {
                float wv = gsw[gg];
                float wh = csw[gg];
                float2 rv2 = RV2[(gg - riv0 + 15)*32 + lane];
                float2 rh2 = RH2[(gg - rih0 + 15)*32 + lane];
                o0.x += wv*rv2.x + wh*rh2.x;
                o0.y += wv*rv2.y + wh*rh2.y;
            }
        }
        {
            float e0 = pw[200];
            float2 rv = RV2[lane];
            float2 rh = RH2[lane];
            o1.x += e0*(rv.x + rh.x);
            o1.y += e0*(rv.y + rh.y);
            #pragma unroll 7
            for (int gg = 0; gg < 14; gg++) {
                float wv = gsw[16+gg];
                float wh = csw[16+gg];
                float2 rv2 = RV2[(gg - riv1 + 15)*32 + lane];
                float2 rh2 = RH2[(gg - rih1 + 15)*32 + lane];
                o1.x += wv*rv2.x + wh*rh2.x;
                o1.y += wv*rv2.y + wh*rh2.y;
            }
        }
        // ---- write output directly as bf16 hi/lo (replaces split_x pass) ----
        if (val0) {
            float inv = 1.0f / sum0;
            float vx = o0.x*inv, vy = o0.y*inv;
            __nv_bfloat16 hx = __float2bfloat16(vx);
            __nv_bfloat16 hy = __float2bfloat16(vy);
            __nv_bfloat16 lx = __float2bfloat16(vx - __bfloat162float(hx));
            __nv_bfloat16 ly = __float2bfloat16(vy - __bfloat162float(hy));
            size_t oidx = base + (size_t)r0*CE + lane*2;
            __nv_bfloat162 hh; hh.x = hx; hh.y = hy;
            __nv_bfloat162 ll; ll.x = lx; ll.y = ly;
            *(__nv_bfloat162*)(&g_Ah[oidx]) = hh;
            *(__nv_bfloat162*)(&g_Al[oidx]) = ll;
        }
        if (val1) {
            float inv = 1.0f / sum1;
            float vx = o1.x*inv, vy = o1.y*inv;
            __nv_bfloat16 hx = __float2bfloat16(vx);
            __nv_bfloat16 hy = __float2bfloat16(vy);
            __nv_bfloat16 lx = __float2bfloat16(vx - __bfloat162float(hx));
            __nv_bfloat16 ly = __float2bfloat16(vy - __bfloat162float(hy));
            size_t oidx = base + (size_t)(r0+1)*CE + lane*2;
            __nv_bfloat162 hh; hh.x = hx; hh.y = hy;
            __nv_bfloat162 ll; ll.x = lx; ll.y = ly;
            *(__nv_bfloat162*)(&g_Ah[oidx]) = hh;
            *(__nv_bfloat162*)(&g_Al[oidx]) = ll;
        }
        __syncwarp();
    }
}

// ---------------------------------------------------------------------------
// Launch: 5 launches total
// ---------------------------------------------------------------------------
extern "C" void kernel_launch(void* const* d_in, const int* in_sizes, int n_in,
                              void* d_out, int out_size)
{
    const float* x     = (const float*)d_in[0];
    const float* wq    = (const float*)d_in[1];
    const float* wk    = (const float*)d_in[2];
    const float* wv    = (const float*)d_in[3];
    const float* wproj = (const float*)d_in[4];
    const float* bproj = (const float*)d_in[5];
    const float* rkv   = (const float*)d_in[6];
    const float* rkh   = (const float*)d_in[7];
    const float* rvv   = (const float*)d_in[8];
    const float* rvh   = (const float*)d_in[9];
    float* out = (float*)d_out;

    float *Qp, *Kp, *Vp;
    __nv_bfloat16 *Ahp, *Alp, *Wthp, *Wtlp;
    cudaGetSymbolAddress((void**)&Qp, g_Q);
    cudaGetSymbolAddress((void**)&Kp, g_K);
    cudaGetSymbolAddress((void**)&Vp, g_V);
    cudaGetSymbolAddress((void**)&Ahp, g_Ah);
    cudaGetSymbolAddress((void**)&Alp, g_Al);
    cudaGetSymbolAddress((void**)&Wthp, g_Wth);
    cudaGetSymbolAddress((void**)&Wtlp, g_Wtl);

    cudaFuncSetAttribute(attn_kernel, cudaFuncAttributeMaxDynamicSharedMemorySize, ASMEM);
    cudaFuncSetAttribute(gemm_mma, cudaFuncAttributeMaxDynamicSharedMemorySize, GEMM_SMEM);

    // 1. all weights transposed+split (one launch)
    transpose_split_w4<<<dim3(CE/32, CE/32, 4), dim3(32, 8)>>>(wq, wk, wv, wproj, Wthp, Wtlp);

    // 2. split x
    int nel = ROWS*CE;
    split_x_kernel<<<(nel+255)/256, 256>>>(x, Ahp, Alp, nel);

    // 3. fused QKV projection (N = 2304)
    gemm_mma<<<dim3(18, (ROWS+127)/128), 256, GEMM_SMEM>>>(
        Ahp, Alp, Wthp, Wtlp, nullptr, Qp, Kp, Vp, ROWS);

    // 4. attention (writes bf16 hi/lo output directly)
    attn_kernel<<<CB*CH, ATHREADS, ASMEM>>>(rkv, rkh, rvv, rvh);

    // 5. output projection (+bias)
    gemm_mma<<<dim3(6, (ROWS+127)/128), 256, GEMM_SMEM>>>(
        Ahp, Alp, Wthp + 3ull*CE*CE, Wtlp + 3ull*CE*CE, bproj, out, nullptr, nullptr, ROWS);
}